// round 2
// baseline (speedup 1.0000x reference)
#include <cuda_runtime.h>
#include <math.h>

// Problem constants (from setup_inputs): B=4, S=2048, D=1024, H=16, dh=64
#define BATCH 4
#define SEQ   2048
#define DMODEL 1024
#define NHEAD 16
#define DHEAD 64

// Scratch (alloc-free rule: __device__ globals)
__device__ float g_Q[(size_t)BATCH * NHEAD * SEQ * DHEAD]; // [b][h][s][d]
__device__ float g_K[(size_t)BATCH * NHEAD * SEQ * DHEAD];
__device__ float g_V[(size_t)BATCH * NHEAD * SEQ * DHEAD];
__device__ float g_A[(size_t)BATCH * SEQ * DMODEL];        // attn out, [b][s][h*64+d]

// ---------------------------------------------------------------------------
// GEMM: C[m][n] = sum_k X[m][k] * W[n][k]   (X: [8192,1024], W: [1024,1024])
// 128x128 block tile, BK=16, 256 threads, 8x8 per-thread register tile.
// MODE 0 (qkv): z selects Wq/Wk/Wv; epilogue applies RoPE (z<2) and writes
//               scratch in [b][h][s][dh] layout.
// MODE 1 (out): plain row-major store to output.
// ---------------------------------------------------------------------------

__global__ __launch_bounds__(256) void qkv_gemm(const float* __restrict__ X,
                                                const float* __restrict__ Wq,
                                                const float* __restrict__ Wk,
                                                const float* __restrict__ Wv)
{
    __shared__ float As[16][128];
    __shared__ float Bs[16][128];

    const int z = blockIdx.z;
    const float* W = (z == 0) ? Wq : ((z == 1) ? Wk : Wv);
    float* Out = (z == 0) ? g_Q : ((z == 1) ? g_K : g_V);

    const int m0 = blockIdx.y * 128;
    const int n0 = blockIdx.x * 128;
    const int tid = threadIdx.x;
    const int tx = tid & 15, ty = tid >> 4;
    const int lr = tid >> 2;            // 0..63
    const int kc = (tid & 3) * 4;       // 0,4,8,12

    float acc[8][8];
    #pragma unroll
    for (int i = 0; i < 8; i++)
        #pragma unroll
        for (int j = 0; j < 8; j++) acc[i][j] = 0.0f;

    const float* Ap = X + (size_t)(m0 + lr) * DMODEL + kc;
    const float* Bp = W + (size_t)(n0 + lr) * DMODEL + kc;

    for (int kt = 0; kt < DMODEL / 16; kt++) {
        float4 a0 = *(const float4*)(Ap);
        float4 a1 = *(const float4*)(Ap + (size_t)64 * DMODEL);
        float4 b0 = *(const float4*)(Bp);
        float4 b1 = *(const float4*)(Bp + (size_t)64 * DMODEL);
        Ap += 16; Bp += 16;

        __syncthreads();
        As[kc + 0][lr] = a0.x; As[kc + 1][lr] = a0.y;
        As[kc + 2][lr] = a0.z; As[kc + 3][lr] = a0.w;
        As[kc + 0][lr + 64] = a1.x; As[kc + 1][lr + 64] = a1.y;
        As[kc + 2][lr + 64] = a1.z; As[kc + 3][lr + 64] = a1.w;
        Bs[kc + 0][lr] = b0.x; Bs[kc + 1][lr] = b0.y;
        Bs[kc + 2][lr] = b0.z; Bs[kc + 3][lr] = b0.w;
        Bs[kc + 0][lr + 64] = b1.x; Bs[kc + 1][lr + 64] = b1.y;
        Bs[kc + 2][lr + 64] = b1.z; Bs[kc + 3][lr + 64] = b1.w;
        __syncthreads();

        #pragma unroll
        for (int k = 0; k < 16; k++) {
            float a[8], b[8];
            *(float4*)(a)     = *(float4*)&As[k][ty * 8];
            *(float4*)(a + 4) = *(float4*)&As[k][ty * 8 + 4];
            *(float4*)(b)     = *(float4*)&Bs[k][tx * 8];
            *(float4*)(b + 4) = *(float4*)&Bs[k][tx * 8 + 4];
            #pragma unroll
            for (int i = 0; i < 8; i++)
                #pragma unroll
                for (int j = 0; j < 8; j++)
                    acc[i][j] = fmaf(a[i], b[j], acc[i][j]);
        }
    }

    // Epilogue: RoPE (for Q,K) + scatter to [b][h][s][dh]
    const int n = n0 + tx * 8;
    const int h = n >> 6;
    const int dq = n & 63;          // 8-col groups never straddle a head (64%8==0)
    const bool rope = (z < 2);

    #pragma unroll
    for (int i = 0; i < 8; i++) {
        const int gm = m0 + ty * 8 + i;
        const int bb = gm >> 11;           // /2048
        const int s  = gm & (SEQ - 1);
        if (rope) {
            #pragma unroll
            for (int c = 0; c < 8; c += 2) {
                const int fi = (dq + c) >> 1;               // 0..31
                const float inv = powf(10000.0f, -(float)fi * (1.0f / 32.0f));
                const float ang = (float)s * inv;
                float sn, cs;
                sincosf(ang, &sn, &cs);
                const float x1 = acc[i][c], x2 = acc[i][c + 1];
                acc[i][c]     = x1 * cs - x2 * sn;
                acc[i][c + 1] = x1 * sn + x2 * cs;
            }
        }
        float* dst = Out + (((size_t)(bb * NHEAD + h) * SEQ + s) * DHEAD + dq);
        *(float4*)(dst)     = make_float4(acc[i][0], acc[i][1], acc[i][2], acc[i][3]);
        *(float4*)(dst + 4) = make_float4(acc[i][4], acc[i][5], acc[i][6], acc[i][7]);
    }
}

__global__ __launch_bounds__(256) void out_gemm(const float* __restrict__ Wo,
                                                float* __restrict__ C)
{
    __shared__ float As[16][128];
    __shared__ float Bs[16][128];

    const int m0 = blockIdx.y * 128;
    const int n0 = blockIdx.x * 128;
    const int tid = threadIdx.x;
    const int tx = tid & 15, ty = tid >> 4;
    const int lr = tid >> 2;
    const int kc = (tid & 3) * 4;

    float acc[8][8];
    #pragma unroll
    for (int i = 0; i < 8; i++)
        #pragma unroll
        for (int j = 0; j < 8; j++) acc[i][j] = 0.0f;

    const float* Ap = g_A + (size_t)(m0 + lr) * DMODEL + kc;
    const float* Bp = Wo  + (size_t)(n0 + lr) * DMODEL + kc;

    for (int kt = 0; kt < DMODEL / 16; kt++) {
        float4 a0 = *(const float4*)(Ap);
        float4 a1 = *(const float4*)(Ap + (size_t)64 * DMODEL);
        float4 b0 = *(const float4*)(Bp);
        float4 b1 = *(const float4*)(Bp + (size_t)64 * DMODEL);
        Ap += 16; Bp += 16;

        __syncthreads();
        As[kc + 0][lr] = a0.x; As[kc + 1][lr] = a0.y;
        As[kc + 2][lr] = a0.z; As[kc + 3][lr] = a0.w;
        As[kc + 0][lr + 64] = a1.x; As[kc + 1][lr + 64] = a1.y;
        As[kc + 2][lr + 64] = a1.z; As[kc + 3][lr + 64] = a1.w;
        Bs[kc + 0][lr] = b0.x; Bs[kc + 1][lr] = b0.y;
        Bs[kc + 2][lr] = b0.z; Bs[kc + 3][lr] = b0.w;
        Bs[kc + 0][lr + 64] = b1.x; Bs[kc + 1][lr + 64] = b1.y;
        Bs[kc + 2][lr + 64] = b1.z; Bs[kc + 3][lr + 64] = b1.w;
        __syncthreads();

        #pragma unroll
        for (int k = 0; k < 16; k++) {
            float a[8], b[8];
            *(float4*)(a)     = *(float4*)&As[k][ty * 8];
            *(float4*)(a + 4) = *(float4*)&As[k][ty * 8 + 4];
            *(float4*)(b)     = *(float4*)&Bs[k][tx * 8];
            *(float4*)(b + 4) = *(float4*)&Bs[k][tx * 8 + 4];
            #pragma unroll
            for (int i = 0; i < 8; i++)
                #pragma unroll
                for (int j = 0; j < 8; j++)
                    acc[i][j] = fmaf(a[i], b[j], acc[i][j]);
        }
    }

    #pragma unroll
    for (int i = 0; i < 8; i++) {
        const int gm = m0 + ty * 8 + i;
        float* dst = C + (size_t)gm * DMODEL + n0 + tx * 8;
        *(float4*)(dst)     = make_float4(acc[i][0], acc[i][1], acc[i][2], acc[i][3]);
        *(float4*)(dst + 4) = make_float4(acc[i][4], acc[i][5], acc[i][6], acc[i][7]);
    }
}

// ---------------------------------------------------------------------------
// Flash attention, fp32. One block per (q-tile of 64, b*h). 256 threads as
// 16x16: score phase -> thread tile 4q x 4k; O phase -> 4q x 4d.
// Smem: Qs[d][q], Ks[d][k] (64x64 transposed), Vs[k][d], Ps[k][q] (stride 68).
// Online softmax stats reduced across tx via width-16 xor shuffles.
// ---------------------------------------------------------------------------
#define FLASH_SMEM_FLOATS (4096 * 3 + 64 * 68)   // 16640 floats = 66560 B

__global__ __launch_bounds__(256) void flash_kernel()
{
    extern __shared__ float sm[];
    float* Qs = sm;             // [64][64]  Qs[d*64+q]
    float* Ks = sm + 4096;      // [64][64]  Ks[d*64+k]
    float* Vs = sm + 8192;      // [64][64]  Vs[k*64+d]
    float* Ps = sm + 12288;     // [64][68]  Ps[k*68+q]

    const int qt = blockIdx.x;
    const int bh = blockIdx.y;
    const float* Qb = g_Q + (size_t)bh * SEQ * DHEAD;
    const float* Kb = g_K + (size_t)bh * SEQ * DHEAD;
    const float* Vb = g_V + (size_t)bh * SEQ * DHEAD;

    const int tid = threadIdx.x;
    const int tx = tid & 15, ty = tid >> 4;
    const int q0 = qt * 64;
    const int lr = tid >> 2;           // 0..63
    const int c0 = (tid & 3) * 4;      // 0,4,8,12

    // Load Q tile transposed, pre-scaled by 1/sqrt(64)
    #pragma unroll
    for (int j = 0; j < 4; j++) {
        const int col = c0 + j * 16;
        float4 v = *(const float4*)(Qb + (size_t)(q0 + lr) * DHEAD + col);
        Qs[(col + 0) * 64 + lr] = v.x * 0.125f;
        Qs[(col + 1) * 64 + lr] = v.y * 0.125f;
        Qs[(col + 2) * 64 + lr] = v.z * 0.125f;
        Qs[(col + 3) * 64 + lr] = v.w * 0.125f;
    }

    float m_i[4], l_i[4], acc[4][4];
    #pragma unroll
    for (int i = 0; i < 4; i++) {
        m_i[i] = -3.0e38f; l_i[i] = 0.0f;
        #pragma unroll
        for (int j = 0; j < 4; j++) acc[i][j] = 0.0f;
    }

    for (int kt = 0; kt <= qt; kt++) {
        const int k0 = kt * 64;
        __syncthreads();   // prev O-accum done (Vs/Ps free), Qs visible on iter 0
        #pragma unroll
        for (int j = 0; j < 4; j++) {
            const int col = c0 + j * 16;
            float4 kv = *(const float4*)(Kb + (size_t)(k0 + lr) * DHEAD + col);
            Ks[(col + 0) * 64 + lr] = kv.x;
            Ks[(col + 1) * 64 + lr] = kv.y;
            Ks[(col + 2) * 64 + lr] = kv.z;
            Ks[(col + 3) * 64 + lr] = kv.w;
            float4 vv = *(const float4*)(Vb + (size_t)(k0 + lr) * DHEAD + col);
            *(float4*)&Vs[lr * 64 + col] = vv;
        }
        __syncthreads();

        // S = Q @ K^T
        float s[4][4];
        #pragma unroll
        for (int i = 0; i < 4; i++)
            #pragma unroll
            for (int j = 0; j < 4; j++) s[i][j] = 0.0f;

        #pragma unroll 16
        for (int d = 0; d < 64; d++) {
            float4 qv = *(float4*)&Qs[d * 64 + ty * 4];
            float4 kv = *(float4*)&Ks[d * 64 + tx * 4];
            const float qa[4] = {qv.x, qv.y, qv.z, qv.w};
            const float ka[4] = {kv.x, kv.y, kv.z, kv.w};
            #pragma unroll
            for (int i = 0; i < 4; i++)
                #pragma unroll
                for (int j = 0; j < 4; j++)
                    s[i][j] = fmaf(qa[i], ka[j], s[i][j]);
        }

        // Causal mask (diagonal tile only)
        if (kt == qt) {
            #pragma unroll
            for (int i = 0; i < 4; i++)
                #pragma unroll
                for (int j = 0; j < 4; j++)
                    if (k0 + tx * 4 + j > q0 + ty * 4 + i) s[i][j] = -3.0e38f;
        }

        // Online softmax
        float alpha[4];
        #pragma unroll
        for (int i = 0; i < 4; i++) {
            float mx = fmaxf(fmaxf(s[i][0], s[i][1]), fmaxf(s[i][2], s[i][3]));
            #pragma unroll
            for (int off = 8; off > 0; off >>= 1)
                mx = fmaxf(mx, __shfl_xor_sync(0xffffffffu, mx, off, 16));
            const float mn = fmaxf(m_i[i], mx);
            alpha[i] = __expf(m_i[i] - mn);
            m_i[i] = mn;
        }
        #pragma unroll
        for (int i = 0; i < 4; i++) {
            float r = 0.0f;
            #pragma unroll
            for (int j = 0; j < 4; j++) {
                const float p = __expf(s[i][j] - m_i[i]);
                s[i][j] = p; r += p;
            }
            #pragma unroll
            for (int off = 8; off > 0; off >>= 1)
                r += __shfl_xor_sync(0xffffffffu, r, off, 16);
            l_i[i] = l_i[i] * alpha[i] + r;
            #pragma unroll
            for (int j = 0; j < 4; j++) acc[i][j] *= alpha[i];
        }

        // Stage P transposed: Ps[k][q]
        #pragma unroll
        for (int j = 0; j < 4; j++)
            *(float4*)&Ps[(tx * 4 + j) * 68 + ty * 4] =
                make_float4(s[0][j], s[1][j], s[2][j], s[3][j]);

        __syncthreads();

        // O += P @ V
        #pragma unroll 16
        for (int k = 0; k < 64; k++) {
            float4 pv = *(float4*)&Ps[k * 68 + ty * 4];
            float4 vv = *(float4*)&Vs[k * 64 + tx * 4];
            const float pa[4] = {pv.x, pv.y, pv.z, pv.w};
            const float va[4] = {vv.x, vv.y, vv.z, vv.w};
            #pragma unroll
            for (int i = 0; i < 4; i++)
                #pragma unroll
                for (int j = 0; j < 4; j++)
                    acc[i][j] = fmaf(pa[i], va[j], acc[i][j]);
        }
    }

    // Normalize + write to [b][s][h*64+d]
    const int b = bh >> 4, h = bh & 15;
    #pragma unroll
    for (int i = 0; i < 4; i++) {
        const float inv = 1.0f / l_i[i];
        const int gq = q0 + ty * 4 + i;
        float* dst = g_A + ((size_t)(b * SEQ + gq)) * DMODEL + h * DHEAD + tx * 4;
        *(float4*)dst = make_float4(acc[i][0] * inv, acc[i][1] * inv,
                                    acc[i][2] * inv, acc[i][3] * inv);
    }
}

// ---------------------------------------------------------------------------

extern "C" void kernel_launch(void* const* d_in, const int* in_sizes, int n_in,
                              void* d_out, int out_size)
{
    const float* x  = (const float*)d_in[0];
    const float* Wq = (const float*)d_in[1];
    const float* Wk = (const float*)d_in[2];
    const float* Wv = (const float*)d_in[3];
    const float* Wo = (const float*)d_in[4];
    float* out = (float*)d_out;

    cudaFuncSetAttribute(flash_kernel, cudaFuncAttributeMaxDynamicSharedMemorySize,
                         FLASH_SMEM_FLOATS * (int)sizeof(float));

    dim3 g1(DMODEL / 128, (BATCH * SEQ) / 128, 3);
    qkv_gemm<<<g1, 256>>>(x, Wq, Wk, Wv);

    flash_kernel<<<dim3(SEQ / 64, BATCH * NHEAD), 256,
                   FLASH_SMEM_FLOATS * (int)sizeof(float)>>>();

    dim3 g2(DMODEL / 128, (BATCH * SEQ) / 128, 1);
    out_gemm<<<g2, 256>>>(Wo, out);
}

// round 3
// speedup vs baseline: 1.0083x; 1.0083x over previous
#include <cuda_runtime.h>
#include <math.h>

// Problem constants (from setup_inputs): B=4, S=2048, D=1024, H=16, dh=64
#define BATCH 4
#define SEQ   2048
#define DMODEL 1024
#define NHEAD 16
#define DHEAD 64

// Scratch (alloc-free rule: __device__ globals)
__device__ float g_Q[(size_t)BATCH * NHEAD * SEQ * DHEAD]; // [b][h][s][d]
__device__ float g_K[(size_t)BATCH * NHEAD * SEQ * DHEAD];
__device__ float g_V[(size_t)BATCH * NHEAD * SEQ * DHEAD];
__device__ float g_A[(size_t)BATCH * SEQ * DMODEL];        // attn out, [b][s][h*64+d]

// ---------------------------------------------------------------------------
// GEMM: C[m][n] = sum_k X[m][k] * W[n][k]   (X: [8192,1024], W: [1024,1024])
// 128x128 block tile, BK=16, 256 threads, 8x8 per-thread register tile.
// MODE 0 (qkv): z selects Wq/Wk/Wv; epilogue applies RoPE (z<2) and writes
//               scratch in [b][h][s][dh] layout.
// MODE 1 (out): plain row-major store to output.
// ---------------------------------------------------------------------------

__global__ __launch_bounds__(256) void qkv_gemm(const float* __restrict__ X,
                                                const float* __restrict__ Wq,
                                                const float* __restrict__ Wk,
                                                const float* __restrict__ Wv)
{
    __shared__ float As[16][128];
    __shared__ float Bs[16][128];

    const int z = blockIdx.z;
    const float* W = (z == 0) ? Wq : ((z == 1) ? Wk : Wv);
    float* Out = (z == 0) ? g_Q : ((z == 1) ? g_K : g_V);

    const int m0 = blockIdx.y * 128;
    const int n0 = blockIdx.x * 128;
    const int tid = threadIdx.x;
    const int tx = tid & 15, ty = tid >> 4;
    const int lr = tid >> 2;            // 0..63
    const int kc = (tid & 3) * 4;       // 0,4,8,12

    float acc[8][8];
    #pragma unroll
    for (int i = 0; i < 8; i++)
        #pragma unroll
        for (int j = 0; j < 8; j++) acc[i][j] = 0.0f;

    const float* Ap = X + (size_t)(m0 + lr) * DMODEL + kc;
    const float* Bp = W + (size_t)(n0 + lr) * DMODEL + kc;

    for (int kt = 0; kt < DMODEL / 16; kt++) {
        float4 a0 = *(const float4*)(Ap);
        float4 a1 = *(const float4*)(Ap + (size_t)64 * DMODEL);
        float4 b0 = *(const float4*)(Bp);
        float4 b1 = *(const float4*)(Bp + (size_t)64 * DMODEL);
        Ap += 16; Bp += 16;

        __syncthreads();
        As[kc + 0][lr] = a0.x; As[kc + 1][lr] = a0.y;
        As[kc + 2][lr] = a0.z; As[kc + 3][lr] = a0.w;
        As[kc + 0][lr + 64] = a1.x; As[kc + 1][lr + 64] = a1.y;
        As[kc + 2][lr + 64] = a1.z; As[kc + 3][lr + 64] = a1.w;
        Bs[kc + 0][lr] = b0.x; Bs[kc + 1][lr] = b0.y;
        Bs[kc + 2][lr] = b0.z; Bs[kc + 3][lr] = b0.w;
        Bs[kc + 0][lr + 64] = b1.x; Bs[kc + 1][lr + 64] = b1.y;
        Bs[kc + 2][lr + 64] = b1.z; Bs[kc + 3][lr + 64] = b1.w;
        __syncthreads();

        #pragma unroll
        for (int k = 0; k < 16; k++) {
            float a[8], b[8];
            *(float4*)(a)     = *(float4*)&As[k][ty * 8];
            *(float4*)(a + 4) = *(float4*)&As[k][ty * 8 + 4];
            *(float4*)(b)     = *(float4*)&Bs[k][tx * 8];
            *(float4*)(b + 4) = *(float4*)&Bs[k][tx * 8 + 4];
            #pragma unroll
            for (int i = 0; i < 8; i++)
                #pragma unroll
                for (int j = 0; j < 8; j++)
                    acc[i][j] = fmaf(a[i], b[j], acc[i][j]);
        }
    }

    // Epilogue: RoPE (for Q,K) + scatter to [b][h][s][dh]
    const int n = n0 + tx * 8;
    const int h = n >> 6;
    const int dq = n & 63;          // 8-col groups never straddle a head (64%8==0)
    const bool rope = (z < 2);

    #pragma unroll
    for (int i = 0; i < 8; i++) {
        const int gm = m0 + ty * 8 + i;
        const int bb = gm >> 11;           // /2048
        const int s  = gm & (SEQ - 1);
        if (rope) {
            #pragma unroll
            for (int c = 0; c < 8; c += 2) {
                const int fi = (dq + c) >> 1;               // 0..31
                const float inv = powf(10000.0f, -(float)fi * (1.0f / 32.0f));
                const float ang = (float)s * inv;
                float sn, cs;
                sincosf(ang, &sn, &cs);
                const float x1 = acc[i][c], x2 = acc[i][c + 1];
                acc[i][c]     = x1 * cs - x2 * sn;
                acc[i][c + 1] = x1 * sn + x2 * cs;
            }
        }
        float* dst = Out + (((size_t)(bb * NHEAD + h) * SEQ + s) * DHEAD + dq);
        *(float4*)(dst)     = make_float4(acc[i][0], acc[i][1], acc[i][2], acc[i][3]);
        *(float4*)(dst + 4) = make_float4(acc[i][4], acc[i][5], acc[i][6], acc[i][7]);
    }
}

__global__ __launch_bounds__(256) void out_gemm(const float* __restrict__ Wo,
                                                float* __restrict__ C)
{
    __shared__ float As[16][128];
    __shared__ float Bs[16][128];

    const int m0 = blockIdx.y * 128;
    const int n0 = blockIdx.x * 128;
    const int tid = threadIdx.x;
    const int tx = tid & 15, ty = tid >> 4;
    const int lr = tid >> 2;
    const int kc = (tid & 3) * 4;

    float acc[8][8];
    #pragma unroll
    for (int i = 0; i < 8; i++)
        #pragma unroll
        for (int j = 0; j < 8; j++) acc[i][j] = 0.0f;

    const float* Ap = g_A + (size_t)(m0 + lr) * DMODEL + kc;
    const float* Bp = Wo  + (size_t)(n0 + lr) * DMODEL + kc;

    for (int kt = 0; kt < DMODEL / 16; kt++) {
        float4 a0 = *(const float4*)(Ap);
        float4 a1 = *(const float4*)(Ap + (size_t)64 * DMODEL);
        float4 b0 = *(const float4*)(Bp);
        float4 b1 = *(const float4*)(Bp + (size_t)64 * DMODEL);
        Ap += 16; Bp += 16;

        __syncthreads();
        As[kc + 0][lr] = a0.x; As[kc + 1][lr] = a0.y;
        As[kc + 2][lr] = a0.z; As[kc + 3][lr] = a0.w;
        As[kc + 0][lr + 64] = a1.x; As[kc + 1][lr + 64] = a1.y;
        As[kc + 2][lr + 64] = a1.z; As[kc + 3][lr + 64] = a1.w;
        Bs[kc + 0][lr] = b0.x; Bs[kc + 1][lr] = b0.y;
        Bs[kc + 2][lr] = b0.z; Bs[kc + 3][lr] = b0.w;
        Bs[kc + 0][lr + 64] = b1.x; Bs[kc + 1][lr + 64] = b1.y;
        Bs[kc + 2][lr + 64] = b1.z; Bs[kc + 3][lr + 64] = b1.w;
        __syncthreads();

        #pragma unroll
        for (int k = 0; k < 16; k++) {
            float a[8], b[8];
            *(float4*)(a)     = *(float4*)&As[k][ty * 8];
            *(float4*)(a + 4) = *(float4*)&As[k][ty * 8 + 4];
            *(float4*)(b)     = *(float4*)&Bs[k][tx * 8];
            *(float4*)(b + 4) = *(float4*)&Bs[k][tx * 8 + 4];
            #pragma unroll
            for (int i = 0; i < 8; i++)
                #pragma unroll
                for (int j = 0; j < 8; j++)
                    acc[i][j] = fmaf(a[i], b[j], acc[i][j]);
        }
    }

    #pragma unroll
    for (int i = 0; i < 8; i++) {
        const int gm = m0 + ty * 8 + i;
        float* dst = C + (size_t)gm * DMODEL + n0 + tx * 8;
        *(float4*)(dst)     = make_float4(acc[i][0], acc[i][1], acc[i][2], acc[i][3]);
        *(float4*)(dst + 4) = make_float4(acc[i][4], acc[i][5], acc[i][6], acc[i][7]);
    }
}

// ---------------------------------------------------------------------------
// Flash attention, fp32. One block per (q-tile of 64, b*h). 256 threads as
// 16x16: score phase -> thread tile 4q x 4k; O phase -> 4q x 4d.
// Smem: Qs[d][q], Ks[d][k] (64x64 transposed), Vs[k][d], Ps[k][q] (stride 68).
// Online softmax stats reduced across tx via width-16 xor shuffles.
// ---------------------------------------------------------------------------
#define FLASH_SMEM_FLOATS (4096 * 3 + 64 * 68)   // 16640 floats = 66560 B

__global__ __launch_bounds__(256) void flash_kernel()
{
    extern __shared__ float sm[];
    float* Qs = sm;             // [64][64]  Qs[d*64+q]
    float* Ks = sm + 4096;      // [64][64]  Ks[d*64+k]
    float* Vs = sm + 8192;      // [64][64]  Vs[k*64+d]
    float* Ps = sm + 12288;     // [64][68]  Ps[k*68+q]

    const int qt = blockIdx.x;
    const int bh = blockIdx.y;
    const float* Qb = g_Q + (size_t)bh * SEQ * DHEAD;
    const float* Kb = g_K + (size_t)bh * SEQ * DHEAD;
    const float* Vb = g_V + (size_t)bh * SEQ * DHEAD;

    const int tid = threadIdx.x;
    const int tx = tid & 15, ty = tid >> 4;
    const int q0 = qt * 64;
    const int lr = tid >> 2;           // 0..63
    const int c0 = (tid & 3) * 4;      // 0,4,8,12

    // Load Q tile transposed, pre-scaled by 1/sqrt(64)
    #pragma unroll
    for (int j = 0; j < 4; j++) {
        const int col = c0 + j * 16;
        float4 v = *(const float4*)(Qb + (size_t)(q0 + lr) * DHEAD + col);
        Qs[(col + 0) * 64 + lr] = v.x * 0.125f;
        Qs[(col + 1) * 64 + lr] = v.y * 0.125f;
        Qs[(col + 2) * 64 + lr] = v.z * 0.125f;
        Qs[(col + 3) * 64 + lr] = v.w * 0.125f;
    }

    float m_i[4], l_i[4], acc[4][4];
    #pragma unroll
    for (int i = 0; i < 4; i++) {
        m_i[i] = -3.0e38f; l_i[i] = 0.0f;
        #pragma unroll
        for (int j = 0; j < 4; j++) acc[i][j] = 0.0f;
    }

    for (int kt = 0; kt <= qt; kt++) {
        const int k0 = kt * 64;
        __syncthreads();   // prev O-accum done (Vs/Ps free), Qs visible on iter 0
        #pragma unroll
        for (int j = 0; j < 4; j++) {
            const int col = c0 + j * 16;
            float4 kv = *(const float4*)(Kb + (size_t)(k0 + lr) * DHEAD + col);
            Ks[(col + 0) * 64 + lr] = kv.x;
            Ks[(col + 1) * 64 + lr] = kv.y;
            Ks[(col + 2) * 64 + lr] = kv.z;
            Ks[(col + 3) * 64 + lr] = kv.w;
            float4 vv = *(const float4*)(Vb + (size_t)(k0 + lr) * DHEAD + col);
            *(float4*)&Vs[lr * 64 + col] = vv;
        }
        __syncthreads();

        // S = Q @ K^T
        float s[4][4];
        #pragma unroll
        for (int i = 0; i < 4; i++)
            #pragma unroll
            for (int j = 0; j < 4; j++) s[i][j] = 0.0f;

        #pragma unroll 16
        for (int d = 0; d < 64; d++) {
            float4 qv = *(float4*)&Qs[d * 64 + ty * 4];
            float4 kv = *(float4*)&Ks[d * 64 + tx * 4];
            const float qa[4] = {qv.x, qv.y, qv.z, qv.w};
            const float ka[4] = {kv.x, kv.y, kv.z, kv.w};
            #pragma unroll
            for (int i = 0; i < 4; i++)
                #pragma unroll
                for (int j = 0; j < 4; j++)
                    s[i][j] = fmaf(qa[i], ka[j], s[i][j]);
        }

        // Causal mask (diagonal tile only)
        if (kt == qt) {
            #pragma unroll
            for (int i = 0; i < 4; i++)
                #pragma unroll
                for (int j = 0; j < 4; j++)
                    if (k0 + tx * 4 + j > q0 + ty * 4 + i) s[i][j] = -3.0e38f;
        }

        // Online softmax
        float alpha[4];
        #pragma unroll
        for (int i = 0; i < 4; i++) {
            float mx = fmaxf(fmaxf(s[i][0], s[i][1]), fmaxf(s[i][2], s[i][3]));
            #pragma unroll
            for (int off = 8; off > 0; off >>= 1)
                mx = fmaxf(mx, __shfl_xor_sync(0xffffffffu, mx, off, 16));
            const float mn = fmaxf(m_i[i], mx);
            alpha[i] = __expf(m_i[i] - mn);
            m_i[i] = mn;
        }
        #pragma unroll
        for (int i = 0; i < 4; i++) {
            float r = 0.0f;
            #pragma unroll
            for (int j = 0; j < 4; j++) {
                const float p = __expf(s[i][j] - m_i[i]);
                s[i][j] = p; r += p;
            }
            #pragma unroll
            for (int off = 8; off > 0; off >>= 1)
                r += __shfl_xor_sync(0xffffffffu, r, off, 16);
            l_i[i] = l_i[i] * alpha[i] + r;
            #pragma unroll
            for (int j = 0; j < 4; j++) acc[i][j] *= alpha[i];
        }

        // Stage P transposed: Ps[k][q]
        #pragma unroll
        for (int j = 0; j < 4; j++)
            *(float4*)&Ps[(tx * 4 + j) * 68 + ty * 4] =
                make_float4(s[0][j], s[1][j], s[2][j], s[3][j]);

        __syncthreads();

        // O += P @ V
        #pragma unroll 16
        for (int k = 0; k < 64; k++) {
            float4 pv = *(float4*)&Ps[k * 68 + ty * 4];
            float4 vv = *(float4*)&Vs[k * 64 + tx * 4];
            const float pa[4] = {pv.x, pv.y, pv.z, pv.w};
            const float va[4] = {vv.x, vv.y, vv.z, vv.w};
            #pragma unroll
            for (int i = 0; i < 4; i++)
                #pragma unroll
                for (int j = 0; j < 4; j++)
                    acc[i][j] = fmaf(pa[i], va[j], acc[i][j]);
        }
    }

    // Normalize + write to [b][s][h*64+d]
    const int b = bh >> 4, h = bh & 15;
    #pragma unroll
    for (int i = 0; i < 4; i++) {
        const float inv = 1.0f / l_i[i];
        const int gq = q0 + ty * 4 + i;
        float* dst = g_A + ((size_t)(b * SEQ + gq)) * DMODEL + h * DHEAD + tx * 4;
        *(float4*)dst = make_float4(acc[i][0] * inv, acc[i][1] * inv,
                                    acc[i][2] * inv, acc[i][3] * inv);
    }
}

// ---------------------------------------------------------------------------

extern "C" void kernel_launch(void* const* d_in, const int* in_sizes, int n_in,
                              void* d_out, int out_size)
{
    const float* x  = (const float*)d_in[0];
    const float* Wq = (const float*)d_in[1];
    const float* Wk = (const float*)d_in[2];
    const float* Wv = (const float*)d_in[3];
    const float* Wo = (const float*)d_in[4];
    float* out = (float*)d_out;

    cudaFuncSetAttribute(flash_kernel, cudaFuncAttributeMaxDynamicSharedMemorySize,
                         FLASH_SMEM_FLOATS * (int)sizeof(float));

    dim3 g1(DMODEL / 128, (BATCH * SEQ) / 128, 3);
    qkv_gemm<<<g1, 256>>>(x, Wq, Wk, Wv);

    flash_kernel<<<dim3(SEQ / 64, BATCH * NHEAD), 256,
                   FLASH_SMEM_FLOATS * (int)sizeof(float)>>>();

    dim3 g2(DMODEL / 128, (BATCH * SEQ) / 128, 1);
    out_gemm<<<g2, 256>>>(Wo, out);
}

// round 4
// speedup vs baseline: 1.0110x; 1.0027x over previous
#include <cuda_runtime.h>
#include <math.h>

// Problem constants (from setup_inputs): B=4, S=2048, D=1024, H=16, dh=64
#define BATCH 4
#define SEQ   2048
#define DMODEL 1024
#define NHEAD 16
#define DHEAD 64

// Scratch (alloc-free rule: __device__ globals)
__device__ float g_Q[(size_t)BATCH * NHEAD * SEQ * DHEAD]; // [b][h][s][d]
__device__ float g_K[(size_t)BATCH * NHEAD * SEQ * DHEAD];
__device__ float g_V[(size_t)BATCH * NHEAD * SEQ * DHEAD];
__device__ float g_A[(size_t)BATCH * SEQ * DMODEL];        // attn out, [b][s][h*64+d]

// ---------------------------------------------------------------------------
// GEMM: C[m][n] = sum_k X[m][k] * W[n][k]   (X: [8192,1024], W: [1024,1024])
// 128x128 block tile, BK=16, 256 threads, 8x8 per-thread register tile.
// MODE 0 (qkv): z selects Wq/Wk/Wv; epilogue applies RoPE (z<2) and writes
//               scratch in [b][h][s][dh] layout.
// MODE 1 (out): plain row-major store to output.
// ---------------------------------------------------------------------------

__global__ __launch_bounds__(256) void qkv_gemm(const float* __restrict__ X,
                                                const float* __restrict__ Wq,
                                                const float* __restrict__ Wk,
                                                const float* __restrict__ Wv)
{
    __shared__ float As[16][128];
    __shared__ float Bs[16][128];

    const int z = blockIdx.z;
    const float* W = (z == 0) ? Wq : ((z == 1) ? Wk : Wv);
    float* Out = (z == 0) ? g_Q : ((z == 1) ? g_K : g_V);

    const int m0 = blockIdx.y * 128;
    const int n0 = blockIdx.x * 128;
    const int tid = threadIdx.x;
    const int tx = tid & 15, ty = tid >> 4;
    const int lr = tid >> 2;            // 0..63
    const int kc = (tid & 3) * 4;       // 0,4,8,12

    float acc[8][8];
    #pragma unroll
    for (int i = 0; i < 8; i++)
        #pragma unroll
        for (int j = 0; j < 8; j++) acc[i][j] = 0.0f;

    const float* Ap = X + (size_t)(m0 + lr) * DMODEL + kc;
    const float* Bp = W + (size_t)(n0 + lr) * DMODEL + kc;

    for (int kt = 0; kt < DMODEL / 16; kt++) {
        float4 a0 = *(const float4*)(Ap);
        float4 a1 = *(const float4*)(Ap + (size_t)64 * DMODEL);
        float4 b0 = *(const float4*)(Bp);
        float4 b1 = *(const float4*)(Bp + (size_t)64 * DMODEL);
        Ap += 16; Bp += 16;

        __syncthreads();
        As[kc + 0][lr] = a0.x; As[kc + 1][lr] = a0.y;
        As[kc + 2][lr] = a0.z; As[kc + 3][lr] = a0.w;
        As[kc + 0][lr + 64] = a1.x; As[kc + 1][lr + 64] = a1.y;
        As[kc + 2][lr + 64] = a1.z; As[kc + 3][lr + 64] = a1.w;
        Bs[kc + 0][lr] = b0.x; Bs[kc + 1][lr] = b0.y;
        Bs[kc + 2][lr] = b0.z; Bs[kc + 3][lr] = b0.w;
        Bs[kc + 0][lr + 64] = b1.x; Bs[kc + 1][lr + 64] = b1.y;
        Bs[kc + 2][lr + 64] = b1.z; Bs[kc + 3][lr + 64] = b1.w;
        __syncthreads();

        #pragma unroll
        for (int k = 0; k < 16; k++) {
            float a[8], b[8];
            *(float4*)(a)     = *(float4*)&As[k][ty * 8];
            *(float4*)(a + 4) = *(float4*)&As[k][ty * 8 + 4];
            *(float4*)(b)     = *(float4*)&Bs[k][tx * 8];
            *(float4*)(b + 4) = *(float4*)&Bs[k][tx * 8 + 4];
            #pragma unroll
            for (int i = 0; i < 8; i++)
                #pragma unroll
                for (int j = 0; j < 8; j++)
                    acc[i][j] = fmaf(a[i], b[j], acc[i][j]);
        }
    }

    // Epilogue: RoPE (for Q,K) + scatter to [b][h][s][dh]
    const int n = n0 + tx * 8;
    const int h = n >> 6;
    const int dq = n & 63;          // 8-col groups never straddle a head (64%8==0)
    const bool rope = (z < 2);

    #pragma unroll
    for (int i = 0; i < 8; i++) {
        const int gm = m0 + ty * 8 + i;
        const int bb = gm >> 11;           // /2048
        const int s  = gm & (SEQ - 1);
        if (rope) {
            #pragma unroll
            for (int c = 0; c < 8; c += 2) {
                const int fi = (dq + c) >> 1;               // 0..31
                const float inv = powf(10000.0f, -(float)fi * (1.0f / 32.0f));
                const float ang = (float)s * inv;
                float sn, cs;
                sincosf(ang, &sn, &cs);
                const float x1 = acc[i][c], x2 = acc[i][c + 1];
                acc[i][c]     = x1 * cs - x2 * sn;
                acc[i][c + 1] = x1 * sn + x2 * cs;
            }
        }
        float* dst = Out + (((size_t)(bb * NHEAD + h) * SEQ + s) * DHEAD + dq);
        *(float4*)(dst)     = make_float4(acc[i][0], acc[i][1], acc[i][2], acc[i][3]);
        *(float4*)(dst + 4) = make_float4(acc[i][4], acc[i][5], acc[i][6], acc[i][7]);
    }
}

__global__ __launch_bounds__(256) void out_gemm(const float* __restrict__ Wo,
                                                float* __restrict__ C)
{
    __shared__ float As[16][128];
    __shared__ float Bs[16][128];

    const int m0 = blockIdx.y * 128;
    const int n0 = blockIdx.x * 128;
    const int tid = threadIdx.x;
    const int tx = tid & 15, ty = tid >> 4;
    const int lr = tid >> 2;
    const int kc = (tid & 3) * 4;

    float acc[8][8];
    #pragma unroll
    for (int i = 0; i < 8; i++)
        #pragma unroll
        for (int j = 0; j < 8; j++) acc[i][j] = 0.0f;

    const float* Ap = g_A + (size_t)(m0 + lr) * DMODEL + kc;
    const float* Bp = Wo  + (size_t)(n0 + lr) * DMODEL + kc;

    for (int kt = 0; kt < DMODEL / 16; kt++) {
        float4 a0 = *(const float4*)(Ap);
        float4 a1 = *(const float4*)(Ap + (size_t)64 * DMODEL);
        float4 b0 = *(const float4*)(Bp);
        float4 b1 = *(const float4*)(Bp + (size_t)64 * DMODEL);
        Ap += 16; Bp += 16;

        __syncthreads();
        As[kc + 0][lr] = a0.x; As[kc + 1][lr] = a0.y;
        As[kc + 2][lr] = a0.z; As[kc + 3][lr] = a0.w;
        As[kc + 0][lr + 64] = a1.x; As[kc + 1][lr + 64] = a1.y;
        As[kc + 2][lr + 64] = a1.z; As[kc + 3][lr + 64] = a1.w;
        Bs[kc + 0][lr] = b0.x; Bs[kc + 1][lr] = b0.y;
        Bs[kc + 2][lr] = b0.z; Bs[kc + 3][lr] = b0.w;
        Bs[kc + 0][lr + 64] = b1.x; Bs[kc + 1][lr + 64] = b1.y;
        Bs[kc + 2][lr + 64] = b1.z; Bs[kc + 3][lr + 64] = b1.w;
        __syncthreads();

        #pragma unroll
        for (int k = 0; k < 16; k++) {
            float a[8], b[8];
            *(float4*)(a)     = *(float4*)&As[k][ty * 8];
            *(float4*)(a + 4) = *(float4*)&As[k][ty * 8 + 4];
            *(float4*)(b)     = *(float4*)&Bs[k][tx * 8];
            *(float4*)(b + 4) = *(float4*)&Bs[k][tx * 8 + 4];
            #pragma unroll
            for (int i = 0; i < 8; i++)
                #pragma unroll
                for (int j = 0; j < 8; j++)
                    acc[i][j] = fmaf(a[i], b[j], acc[i][j]);
        }
    }

    #pragma unroll
    for (int i = 0; i < 8; i++) {
        const int gm = m0 + ty * 8 + i;
        float* dst = C + (size_t)gm * DMODEL + n0 + tx * 8;
        *(float4*)(dst)     = make_float4(acc[i][0], acc[i][1], acc[i][2], acc[i][3]);
        *(float4*)(dst + 4) = make_float4(acc[i][4], acc[i][5], acc[i][6], acc[i][7]);
    }
}

// ---------------------------------------------------------------------------
// Flash attention, fp32. One block per (q-tile of 64, b*h). 256 threads as
// 16x16: score phase -> thread tile 4q x 4k; O phase -> 4q x 4d.
// Smem: Qs[d][q], Ks[d][k] (64x64 transposed), Vs[k][d], Ps[k][q] (stride 68).
// Online softmax stats reduced across tx via width-16 xor shuffles.
// ---------------------------------------------------------------------------
#define FLASH_SMEM_FLOATS (4096 * 3 + 64 * 68)   // 16640 floats = 66560 B

__global__ __launch_bounds__(256) void flash_kernel()
{
    extern __shared__ float sm[];
    float* Qs = sm;             // [64][64]  Qs[d*64+q]
    float* Ks = sm + 4096;      // [64][64]  Ks[d*64+k]
    float* Vs = sm + 8192;      // [64][64]  Vs[k*64+d]
    float* Ps = sm + 12288;     // [64][68]  Ps[k*68+q]

    const int qt = blockIdx.x;
    const int bh = blockIdx.y;
    const float* Qb = g_Q + (size_t)bh * SEQ * DHEAD;
    const float* Kb = g_K + (size_t)bh * SEQ * DHEAD;
    const float* Vb = g_V + (size_t)bh * SEQ * DHEAD;

    const int tid = threadIdx.x;
    const int tx = tid & 15, ty = tid >> 4;
    const int q0 = qt * 64;
    const int lr = tid >> 2;           // 0..63
    const int c0 = (tid & 3) * 4;      // 0,4,8,12

    // Load Q tile transposed, pre-scaled by 1/sqrt(64)
    #pragma unroll
    for (int j = 0; j < 4; j++) {
        const int col = c0 + j * 16;
        float4 v = *(const float4*)(Qb + (size_t)(q0 + lr) * DHEAD + col);
        Qs[(col + 0) * 64 + lr] = v.x * 0.125f;
        Qs[(col + 1) * 64 + lr] = v.y * 0.125f;
        Qs[(col + 2) * 64 + lr] = v.z * 0.125f;
        Qs[(col + 3) * 64 + lr] = v.w * 0.125f;
    }

    float m_i[4], l_i[4], acc[4][4];
    #pragma unroll
    for (int i = 0; i < 4; i++) {
        m_i[i] = -3.0e38f; l_i[i] = 0.0f;
        #pragma unroll
        for (int j = 0; j < 4; j++) acc[i][j] = 0.0f;
    }

    for (int kt = 0; kt <= qt; kt++) {
        const int k0 = kt * 64;
        __syncthreads();   // prev O-accum done (Vs/Ps free), Qs visible on iter 0
        #pragma unroll
        for (int j = 0; j < 4; j++) {
            const int col = c0 + j * 16;
            float4 kv = *(const float4*)(Kb + (size_t)(k0 + lr) * DHEAD + col);
            Ks[(col + 0) * 64 + lr] = kv.x;
            Ks[(col + 1) * 64 + lr] = kv.y;
            Ks[(col + 2) * 64 + lr] = kv.z;
            Ks[(col + 3) * 64 + lr] = kv.w;
            float4 vv = *(const float4*)(Vb + (size_t)(k0 + lr) * DHEAD + col);
            *(float4*)&Vs[lr * 64 + col] = vv;
        }
        __syncthreads();

        // S = Q @ K^T
        float s[4][4];
        #pragma unroll
        for (int i = 0; i < 4; i++)
            #pragma unroll
            for (int j = 0; j < 4; j++) s[i][j] = 0.0f;

        #pragma unroll 16
        for (int d = 0; d < 64; d++) {
            float4 qv = *(float4*)&Qs[d * 64 + ty * 4];
            float4 kv = *(float4*)&Ks[d * 64 + tx * 4];
            const float qa[4] = {qv.x, qv.y, qv.z, qv.w};
            const float ka[4] = {kv.x, kv.y, kv.z, kv.w};
            #pragma unroll
            for (int i = 0; i < 4; i++)
                #pragma unroll
                for (int j = 0; j < 4; j++)
                    s[i][j] = fmaf(qa[i], ka[j], s[i][j]);
        }

        // Causal mask (diagonal tile only)
        if (kt == qt) {
            #pragma unroll
            for (int i = 0; i < 4; i++)
                #pragma unroll
                for (int j = 0; j < 4; j++)
                    if (k0 + tx * 4 + j > q0 + ty * 4 + i) s[i][j] = -3.0e38f;
        }

        // Online softmax
        float alpha[4];
        #pragma unroll
        for (int i = 0; i < 4; i++) {
            float mx = fmaxf(fmaxf(s[i][0], s[i][1]), fmaxf(s[i][2], s[i][3]));
            #pragma unroll
            for (int off = 8; off > 0; off >>= 1)
                mx = fmaxf(mx, __shfl_xor_sync(0xffffffffu, mx, off, 16));
            const float mn = fmaxf(m_i[i], mx);
            alpha[i] = __expf(m_i[i] - mn);
            m_i[i] = mn;
        }
        #pragma unroll
        for (int i = 0; i < 4; i++) {
            float r = 0.0f;
            #pragma unroll
            for (int j = 0; j < 4; j++) {
                const float p = __expf(s[i][j] - m_i[i]);
                s[i][j] = p; r += p;
            }
            #pragma unroll
            for (int off = 8; off > 0; off >>= 1)
                r += __shfl_xor_sync(0xffffffffu, r, off, 16);
            l_i[i] = l_i[i] * alpha[i] + r;
            #pragma unroll
            for (int j = 0; j < 4; j++) acc[i][j] *= alpha[i];
        }

        // Stage P transposed: Ps[k][q]
        #pragma unroll
        for (int j = 0; j < 4; j++)
            *(float4*)&Ps[(tx * 4 + j) * 68 + ty * 4] =
                make_float4(s[0][j], s[1][j], s[2][j], s[3][j]);

        __syncthreads();

        // O += P @ V
        #pragma unroll 16
        for (int k = 0; k < 64; k++) {
            float4 pv = *(float4*)&Ps[k * 68 + ty * 4];
            float4 vv = *(float4*)&Vs[k * 64 + tx * 4];
            const float pa[4] = {pv.x, pv.y, pv.z, pv.w};
            const float va[4] = {vv.x, vv.y, vv.z, vv.w};
            #pragma unroll
            for (int i = 0; i < 4; i++)
                #pragma unroll
                for (int j = 0; j < 4; j++)
                    acc[i][j] = fmaf(pa[i], va[j], acc[i][j]);
        }
    }

    // Normalize + write to [b][s][h*64+d]
    const int b = bh >> 4, h = bh & 15;
    #pragma unroll
    for (int i = 0; i < 4; i++) {
        const float inv = 1.0f / l_i[i];
        const int gq = q0 + ty * 4 + i;
        float* dst = g_A + ((size_t)(b * SEQ + gq)) * DMODEL + h * DHEAD + tx * 4;
        *(float4*)dst = make_float4(acc[i][0] * inv, acc[i][1] * inv,
                                    acc[i][2] * inv, acc[i][3] * inv);
    }
}

// ---------------------------------------------------------------------------

extern "C" void kernel_launch(void* const* d_in, const int* in_sizes, int n_in,
                              void* d_out, int out_size)
{
    const float* x  = (const float*)d_in[0];
    const float* Wq = (const float*)d_in[1];
    const float* Wk = (const float*)d_in[2];
    const float* Wv = (const float*)d_in[3];
    const float* Wo = (const float*)d_in[4];
    float* out = (float*)d_out;

    cudaFuncSetAttribute(flash_kernel, cudaFuncAttributeMaxDynamicSharedMemorySize,
                         FLASH_SMEM_FLOATS * (int)sizeof(float));

    dim3 g1(DMODEL / 128, (BATCH * SEQ) / 128, 3);
    qkv_gemm<<<g1, 256>>>(x, Wq, Wk, Wv);

    flash_kernel<<<dim3(SEQ / 64, BATCH * NHEAD), 256,
                   FLASH_SMEM_FLOATS * (int)sizeof(float)>>>();

    dim3 g2(DMODEL / 128, (BATCH * SEQ) / 128, 1);
    out_gemm<<<g2, 256>>>(Wo, out);
}